// round 5
// baseline (speedup 1.0000x reference)
#include <cuda_runtime.h>

#define BN 256
#define TN 512
#define CN 128
#define FN 128
#define NB 32

typedef unsigned long long ull;

__device__ __forceinline__ ull pk2(float lo, float hi) {
    ull r; asm("mov.b64 %0, {%1, %2};" : "=l"(r) : "f"(lo), "f"(hi)); return r;
}
__device__ __forceinline__ void upk2(ull v, float& lo, float& hi) {
    asm("mov.b64 {%0, %1}, %2;" : "=f"(lo), "=f"(hi) : "l"(v));
}
__device__ __forceinline__ ull fma2(ull a, ull b, ull c) {
    ull d; asm("fma.rn.f32x2 %0, %1, %2, %3;" : "=l"(d) : "l"(a), "l"(b), "l"(c)); return d;
}
__device__ __forceinline__ float wsum(float v) {
    #pragma unroll
    for (int o = 16; o; o >>= 1) v += __shfl_xor_sync(0xffffffffu, v, o);
    return v;
}

// ============================================================
// Conv1D: y[b][t][f] = sum_{k,c} x[b][t+k-1][c] * W[k][c][f] + bias[f]
// Single X staging per c0 chunk, all 3 taps resident.
// ============================================================
#define CONV_SM ((66 * 33 + 3 * 32 * 128) * 4)

__global__ __launch_bounds__(256) void conv_kernel(
    const float* __restrict__ x, const float* __restrict__ W,
    const float* __restrict__ bias, float* __restrict__ y)
{
    extern __shared__ float csm[];
    float (*Xs)[33]      = (float (*)[33])csm;              // 66 x 33
    float (*Ws)[32][128] = (float (*)[32][128])(csm + 66 * 33);

    const int b = blockIdx.y, t0 = blockIdx.x * 64, tid = threadIdx.x;
    const int lane = tid & 31, warp = tid >> 5;
    const int cbase = lane * 4, rbase = warp * 8;

    ull acc2[8][2];
    #pragma unroll
    for (int i = 0; i < 8; i++) { acc2[i][0] = 0ull; acc2[i][1] = 0ull; }

    for (int c0 = 0; c0 < CN; c0 += 32) {
        #pragma unroll
        for (int q = 0; q < 48; q++) {
            int e = tid + 256 * q;
            int f = e & 127, rest = e >> 7;
            int cc = rest & 31, k = rest >> 5;
            Ws[k][cc][f] = W[((size_t)(k * CN + c0 + cc)) * FN + f];
        }
        #pragma unroll
        for (int q = 0; q < 9; q++) {
            int e = tid + 256 * q;
            if (e < 66 * 32) {
                int cc = e & 31, r = e >> 5;
                int t = t0 - 1 + r;
                float v = (t >= 0 && t < TN) ? x[((size_t)b * TN + t) * CN + c0 + cc] : 0.f;
                Xs[r][cc] = v;
            }
        }
        __syncthreads();
        #pragma unroll 4
        for (int cc = 0; cc < 32; cc++) {
            ull w01[3], w23[3];
            #pragma unroll
            for (int k = 0; k < 3; k++) {
                const ull* wp = (const ull*)&Ws[k][cc][cbase];
                w01[k] = wp[0]; w23[k] = wp[1];
            }
            float xr[10];
            #pragma unroll
            for (int r = 0; r < 10; r++) xr[r] = Xs[rbase + r][cc];
            #pragma unroll
            for (int i = 0; i < 8; i++) {
                #pragma unroll
                for (int k = 0; k < 3; k++) {
                    ull xx = pk2(xr[i + k], xr[i + k]);
                    acc2[i][0] = fma2(xx, w01[k], acc2[i][0]);
                    acc2[i][1] = fma2(xx, w23[k], acc2[i][1]);
                }
            }
        }
        __syncthreads();
    }
    float b0 = bias[cbase], b1 = bias[cbase+1], b2 = bias[cbase+2], b3 = bias[cbase+3];
    #pragma unroll
    for (int i = 0; i < 8; i++) {
        int t = t0 + rbase + i;
        float4 o; float lo, hi;
        upk2(acc2[i][0], lo, hi); o.x = lo + b0; o.y = hi + b1;
        upk2(acc2[i][1], lo, hi); o.z = lo + b2; o.w = hi + b3;
        *(float4*)&y[((size_t)b * TN + t) * FN + cbase] = o;
    }
}

// ============================================================
// Blocked Householder QR (WY), one CTA per 512x128 matrix.
// Vp stored stride-32 with GROUP-of-4 XOR swizzle: 16B block ig of row t
// lives at byte offset t*128 + (((ig ^ t) & 7) << 4).
//  - row access (varying i, fixed t): conflict-free, LDS.128-able
//  - column access (varying t, fixed i): 4-way (panel phase only)
// ============================================================
#define VP(t,i)   Vp[((t) << 5) + (((((i) >> 2) ^ (t)) & 7) << 2) + ((i) & 3)]
#define W2STRIDE  144   /* 32 rows x (12 groups x 12 floats) */

template<int WT, bool TRANS>
__device__ void block_apply(float* __restrict__ G, int o, int colbase,
                            const float* __restrict__ Vp, const float* __restrict__ Tp,
                            float* __restrict__ Wm, float* __restrict__ Wm2, int tid)
{
    const int lane = tid & 31, w = tid >> 5;
    constexpr int NU = WT / 32;      // ull per warp-row in GEMM1
    constexpr int HW = WT / 2;       // ull per staged row
    constexpr int TU = 16 * HW;      // ull per 16-row tile
    ull* Gs = (ull*)Wm2;             // staging buffer overlays Wm2

    // ---- GEMM1: Wm[i][c] = sum_t V[t][i]*G[t][colbase+c] (SMEM staged) ----
    ull acc[NU];
    #pragma unroll
    for (int k = 0; k < NU; k++) acc[k] = 0ull;
    const int ntiles = (TN - o) >> 4;
    for (int tile = 0; tile < ntiles; tile++) {
        const int t0 = o + (tile << 4);
        for (int u = tid; u < TU; u += 512) {
            int r = u / HW, c = u - r * HW;
            Gs[u] = *(const ull*)(G + (size_t)(t0 + r) * FN + colbase + 2 * c);
        }
        __syncthreads();
        #pragma unroll
        for (int r = 0; r < 16; r++) {
            float v = VP(t0 + r, lane);
            ull vv = pk2(v, v);
            const ull* g = Gs + r * HW + w * NU;
            #pragma unroll
            for (int k = 0; k < NU; k++) acc[k] = fma2(vv, g[k], acc[k]);
        }
        __syncthreads();
    }
    {
        ull* wout = (ull*)(Wm + lane * 96) + w * NU;
        #pragma unroll
        for (int k = 0; k < NU; k++) wout[k] = acc[k];
    }
    __syncthreads();

    // ---- Tapply: Wm2[i][grp12] = -(T^op * Wm)[i][grp8] ----
    {
        constexpr int NCG = WT / 8;
        for (int pos = tid; pos < 32 * NCG * 4; pos += 512) {
            int i = pos / (NCG * 4);
            int rem = pos - i * (NCG * 4);
            int cg = rem >> 2, k = rem & 3;
            int c = cg * 8 + 2 * k;
            ull a = 0ull;
            #pragma unroll
            for (int j = 0; j < 32; j++) {
                float tv = TRANS ? Tp[j * 33 + i] : Tp[i * 33 + j];
                a = fma2(pk2(-tv, -tv), *(const ull*)(Wm + j * 96 + c), a);
            }
            *(ull*)(Wm2 + i * W2STRIDE + cg * 12 + 2 * k) = a;
        }
    }
    __syncthreads();

    // ---- GEMM2: G += V * Wm2, 4 rows x 8 cols per thread, LDS.128 ----
    {
        constexpr int NCG = WT / 8;
        const int npos = ((TN - o) >> 2) * NCG;
        for (int pos = tid; pos < npos; pos += 512) {
            int tg = pos / NCG, cg = pos - tg * NCG;
            int t0 = o + (tg << 2);
            float* gp = G + (size_t)t0 * FN + colbase + cg * 8;
            ull a[4][4];
            #pragma unroll
            for (int r = 0; r < 4; r++) {
                ulonglong2 q0 = ((const ulonglong2*)(gp + r * FN))[0];
                ulonglong2 q1 = ((const ulonglong2*)(gp + r * FN))[1];
                a[r][0] = q0.x; a[r][1] = q0.y; a[r][2] = q1.x; a[r][3] = q1.y;
            }
            const float* w2base = Wm2 + cg * 12;
            #pragma unroll
            for (int ig = 0; ig < 8; ig++) {
                float4 v4[4];
                #pragma unroll
                for (int r = 0; r < 4; r++) {
                    int t = t0 + r;
                    v4[r] = *(const float4*)(Vp + (t << 5) + (((ig ^ t) & 7) << 2));
                }
                #pragma unroll
                for (int ii = 0; ii < 4; ii++) {
                    const ull* wp = (const ull*)(w2base + (ig * 4 + ii) * W2STRIDE);
                    ull w0 = wp[0], w1 = wp[1], w2 = wp[2], w3 = wp[3];
                    #pragma unroll
                    for (int r = 0; r < 4; r++) {
                        float vs = (ii == 0) ? v4[r].x : (ii == 1) ? v4[r].y
                                 : (ii == 2) ? v4[r].z : v4[r].w;
                        ull vv = pk2(vs, vs);
                        a[r][0] = fma2(vv, w0, a[r][0]);
                        a[r][1] = fma2(vv, w1, a[r][1]);
                        a[r][2] = fma2(vv, w2, a[r][2]);
                        a[r][3] = fma2(vv, w3, a[r][3]);
                    }
                }
            }
            #pragma unroll
            for (int r = 0; r < 4; r++) {
                ulonglong2 q0, q1;
                q0.x = a[r][0]; q0.y = a[r][1]; q1.x = a[r][2]; q1.y = a[r][3];
                ((ulonglong2*)(gp + r * FN))[0] = q0;
                ((ulonglong2*)(gp + r * FN))[1] = q1;
            }
        }
    }
    __syncthreads();
}

__device__ void panel_factor(float* Vp, float* taus, float* sred, float* wred,
                             float* scal, int o, int tid)
{
    const int lane = tid & 31, w = tid >> 5;
    for (int i = 0; i < NB; i++) {
        const int prow = o + i;
        float val = 0.f;
        if (tid >= prow) val = VP(tid, i);
        if (tid == prow) scal[0] = val;
        float sq = (tid > prow) ? val * val : 0.f;
        sq = wsum(sq);
        if (lane == 0) sred[w] = sq;
        __syncthreads();
        if (tid == 0) {
            float s2 = 0.f;
            #pragma unroll
            for (int k = 0; k < 16; k++) s2 += sred[k];
            float alpha = scal[0], tau, sc;
            if (s2 == 0.f) { tau = 0.f; sc = 0.f; }
            else {
                float beta = -copysignf(sqrtf(alpha * alpha + s2), alpha);
                tau = (beta - alpha) / beta;
                sc = 1.f / (alpha - beta);
            }
            scal[1] = tau; scal[2] = sc; taus[o + i] = tau;
        }
        __syncthreads();
        const float tau = scal[1], sc = scal[2];
        if (tid > prow)       VP(tid, i) = val * sc;
        else if (tid == prow) VP(tid, i) = 1.f;
        __syncthreads();
        if (tau != 0.f && i < NB - 1) {
            const int c0 = w, c1 = w + 16;
            float p0 = 0.f, p1 = 0.f;
            for (int t = prow + lane; t < TN; t += 32) {
                float vi = VP(t, i);
                p0 += vi * VP(t, c0);
                p1 += vi * VP(t, c1);
            }
            p0 = wsum(p0); p1 = wsum(p1);
            if (lane == 0) { wred[c0] = p0; wred[c1] = p1; }
            __syncthreads();
            float tw = tau * wred[lane];
            if (lane > i) {
                for (int t = prow + w; t < TN; t += 16)
                    VP(t, lane) -= tw * VP(t, i);
            }
            __syncthreads();
        }
    }
}

__device__ void build_T(const float* Vp, float* B, float* Tp, const float* taus,
                        int o, int tid)
{
    const int lane = tid & 31, w = tid >> 5;
    for (int i = 1; i < NB; i++) {
        for (int j = w; j < i; j += 16) {
            float p = 0.f;
            for (int t = o + i + lane; t < TN; t += 32)
                p += VP(t, j) * VP(t, i);
            p = wsum(p);
            if (lane == 0) B[j * 32 + i] = p;
        }
    }
    __syncthreads();
    if (w == 0) {
        for (int i = 0; i < NB; i++) {
            float ti = taus[o + i];
            float a = 0.f;
            for (int k = 0; k < i; k++)
                a += Tp[lane * 33 + k] * B[k * 32 + i];
            float tv = (lane < i) ? -ti * a : (lane == i ? ti : 0.f);
            Tp[lane * 33 + i] = tv;
            __syncwarp();
        }
    }
    __syncthreads();
}

// orgqr panel formation: Q[:, o:o+32] = E_p - V * (T * L0^T)
__device__ void form_panel(float* G, const float* Vp, const float* Tp,
                           float* M, int o, int tid)
{
    const int lane = tid & 31, w = tid >> 5;
    for (int pos = tid; pos < 32 * 32; pos += 512) {
        int i = pos >> 5, c = pos & 31;
        float a = 0.f;
        #pragma unroll 8
        for (int j = 0; j < 32; j++)
            a += Tp[i * 33 + j] * VP(o + c, j);
        M[i * 32 + c] = a;
    }
    __syncthreads();
    for (int t = o + w; t < TN; t += 16) {
        float q = (t == o + lane) ? 1.f : 0.f;
        #pragma unroll 8
        for (int j = 0; j < 32; j++)
            q -= VP(t, j) * M[j * 32 + lane];
        G[(size_t)t * FN + o + lane] = q;
    }
    for (int idx = tid; idx < o * 32; idx += 512) {
        int t = idx >> 5, c = idx & 31;
        G[(size_t)t * FN + o + c] = 0.f;
    }
    __syncthreads();
}

// SMEM (floats): Vp 16384 | Ts 4224 | Wm 3072 | Wm2 4608 | taus 128 | sred 16 | wred 32 | scal 4
#define SM_FLOATS (16384 + 4224 + 3072 + 4608 + 128 + 16 + 32 + 4)
#define SM_BYTES  (SM_FLOATS * 4)

__global__ __launch_bounds__(512, 2) void qr_kernel(float* __restrict__ Aall)
{
    extern __shared__ float sm[];
    float* Vp   = sm;
    float* Ts   = Vp + 16384;
    float* Wm   = Ts + 4224;
    float* Wm2  = Wm + 3072;          // also GEMM1 staging + build_T B
    float* taus = Wm2 + 4608;
    float* sred = taus + 128;
    float* wred = sred + 16;
    float* scal = wred + 32;

    const int b = blockIdx.x;
    float* A = Aall + (size_t)b * TN * FN;
    const int tid = threadIdx.x;
    const int lane = tid & 31, w = tid >> 5;

    // ---------------- geqrf (blocked) ----------------
    for (int p = 0; p < 4; p++) {
        const int o = p * 32;
        for (int t = o + w; t < TN; t += 16)
            VP(t, lane) = A[(size_t)t * FN + o + lane];
        __syncthreads();
        panel_factor(Vp, taus, sred, wred, scal, o, tid);
        for (int pos = tid; pos < 32 * 32; pos += 512) {
            int i = pos >> 5, r = pos & 31;
            if (r < i) VP(o + r, i) = 0.f;
        }
        __syncthreads();
        float* Tp = Ts + p * 1056;
        build_T(Vp, Wm2, Tp, taus, o, tid);
        if (p == 0)      block_apply<96, true>(A, 0,  32,  Vp, Tp, Wm, Wm2, tid);
        else if (p == 1) block_apply<64, true>(A, 32, 64,  Vp, Tp, Wm, Wm2, tid);
        else if (p == 2) block_apply<32, true>(A, 64, 96,  Vp, Tp, Wm, Wm2, tid);
        if (p != 3) {   // panel 3 stays resident in SMEM for orgqr
            for (int t = o + w; t < TN; t += 16)
                A[(size_t)t * FN + o + lane] = VP(t, lane);
            __syncthreads();
        }
    }

    // ---------------- orgqr (blocked, backward) ----------------
    for (int p = 3; p >= 0; p--) {
        const int o = p * 32;
        if (p != 3) {
            for (int t = o + w; t < TN; t += 16)
                VP(t, lane) = A[(size_t)t * FN + o + lane];
            __syncthreads();
        }
        const float* Tp = Ts + p * 1056;
        if (p == 0)      block_apply<96, false>(A, 0,  32, Vp, Tp, Wm, Wm2, tid);
        else if (p == 1) block_apply<64, false>(A, 32, 64, Vp, Tp, Wm, Wm2, tid);
        else if (p == 2) block_apply<32, false>(A, 64, 96, Vp, Tp, Wm, Wm2, tid);
        form_panel(A, Vp, Tp, Wm, o, tid);
    }
}

// ============================================================
extern "C" void kernel_launch(void* const* d_in, const int* in_sizes, int n_in,
                              void* d_out, int out_size)
{
    const float* x    = (const float*)d_in[0];
    const float* W    = (const float*)d_in[1];
    const float* bias = (const float*)d_in[2];
    float* out = (float*)d_out;

    cudaFuncSetAttribute(qr_kernel, cudaFuncAttributeMaxDynamicSharedMemorySize, SM_BYTES);
    cudaFuncSetAttribute(conv_kernel, cudaFuncAttributeMaxDynamicSharedMemorySize, CONV_SM);

    dim3 cgrid(TN / 64, BN);
    conv_kernel<<<cgrid, 256, CONV_SM>>>(x, W, bias, out);
    qr_kernel<<<BN, 512, SM_BYTES>>>(out);
}

// round 6
// speedup vs baseline: 1.6908x; 1.6908x over previous
#include <cuda_runtime.h>

#define BN 256
#define TN 512
#define CN 128
#define FN 128
#define NB 32

typedef unsigned long long ull;

__device__ __forceinline__ ull pk2(float lo, float hi) {
    ull r; asm("mov.b64 %0, {%1, %2};" : "=l"(r) : "f"(lo), "f"(hi)); return r;
}
__device__ __forceinline__ void upk2(ull v, float& lo, float& hi) {
    asm("mov.b64 {%0, %1}, %2;" : "=f"(lo), "=f"(hi) : "l"(v));
}
__device__ __forceinline__ ull fma2(ull a, ull b, ull c) {
    ull d; asm("fma.rn.f32x2 %0, %1, %2, %3;" : "=l"(d) : "l"(a), "l"(b), "l"(c)); return d;
}
__device__ __forceinline__ float wsum(float v) {
    #pragma unroll
    for (int o = 16; o; o >>= 1) v += __shfl_xor_sync(0xffffffffu, v, o);
    return v;
}

// ============================================================
// Conv1D: y[b][t][f] = sum_{k,c} x[b][t+k-1][c] * W[k][c][f] + bias[f]
// ============================================================
__global__ __launch_bounds__(256) void conv_kernel(
    const float* __restrict__ x, const float* __restrict__ W,
    const float* __restrict__ bias, float* __restrict__ y)
{
    __shared__ float Xs[64][33];
    __shared__ float Ws[32][128];

    const int b = blockIdx.y, t0 = blockIdx.x * 64, tid = threadIdx.x;
    const int lane = tid & 31, warp = tid >> 5;
    const int cbase = lane * 4, rbase = warp * 8;

    ull acc2[8][2];
    #pragma unroll
    for (int i = 0; i < 8; i++) { acc2[i][0] = 0ull; acc2[i][1] = 0ull; }

    for (int k = 0; k < 3; k++) {
        for (int c0 = 0; c0 < CN; c0 += 32) {
            #pragma unroll
            for (int q = 0; q < 16; q++) {
                int e = tid + 256 * q, f = e & 127, cc = e >> 7;
                Ws[cc][f] = W[((size_t)(k * CN + c0 + cc)) * FN + f];
            }
            #pragma unroll
            for (int q = 0; q < 8; q++) {
                int e = tid + 256 * q, cc = e & 31, r = e >> 5;
                int t = t0 + r + k - 1;
                float v = 0.f;
                if (t >= 0 && t < TN) v = x[((size_t)b * TN + t) * CN + c0 + cc];
                Xs[r][cc] = v;
            }
            __syncthreads();
            #pragma unroll
            for (int cc = 0; cc < 32; cc++) {
                const ull* wp = (const ull*)&Ws[cc][cbase];
                ull w01 = wp[0], w23 = wp[1];
                #pragma unroll
                for (int i = 0; i < 8; i++) {
                    float xv = Xs[rbase + i][cc];
                    ull xx = pk2(xv, xv);
                    acc2[i][0] = fma2(xx, w01, acc2[i][0]);
                    acc2[i][1] = fma2(xx, w23, acc2[i][1]);
                }
            }
            __syncthreads();
        }
    }
    float b0 = bias[cbase], b1 = bias[cbase+1], b2 = bias[cbase+2], b3 = bias[cbase+3];
    #pragma unroll
    for (int i = 0; i < 8; i++) {
        int t = t0 + rbase + i;
        float4 o; float lo, hi;
        upk2(acc2[i][0], lo, hi); o.x = lo + b0; o.y = hi + b1;
        upk2(acc2[i][1], lo, hi); o.z = lo + b2; o.w = hi + b3;
        *(float4*)&y[((size_t)b * TN + t) * FN + cbase] = o;
    }
}

// ============================================================
// Blocked Householder QR (WY), one CTA per 512x128 matrix.
// Vp stride-33: conflict-free banks in BOTH row and column access,
// zero swizzle ALU (column index folds into LDS immediate offsets).
// ============================================================
#define VP(t,i)   Vp[(t) * 33 + (i)]
#define W2STRIDE  120   /* 32 rows x (12 groups x 10 floats) */

template<int WT, bool TRANS>
__device__ void block_apply(float* __restrict__ G, int o, int colbase,
                            const float* __restrict__ Vp, const float* __restrict__ Tp,
                            float* __restrict__ Wm, float* __restrict__ Wm2, int tid)
{
    const int lane = tid & 31, w = tid >> 5;
    constexpr int NU = WT / 32;      // ull per warp-row in GEMM1
    constexpr int HW = WT / 2;       // ull per staged row
    constexpr int TU = 32 * HW;      // ull per 32-row tile
    ull* Gs = (ull*)Wm2;             // staging buffer overlays Wm2

    // ---- GEMM1: Wm[i][c] = sum_t V[t][i]*G[t][colbase+c] (SMEM staged) ----
    ull acc[NU];
    #pragma unroll
    for (int k = 0; k < NU; k++) acc[k] = 0ull;
    const int ntiles = (TN - o) >> 5;
    for (int tile = 0; tile < ntiles; tile++) {
        const int t0 = o + (tile << 5);
        #pragma unroll
        for (int u = tid; u < TU; u += 512) {
            int r = u / HW, c = u - r * HW;
            Gs[u] = *(const ull*)(G + (size_t)(t0 + r) * FN + colbase + 2 * c);
        }
        __syncthreads();
        #pragma unroll
        for (int r = 0; r < 32; r++) {
            float v = VP(t0 + r, lane);
            ull vv = pk2(v, v);
            const ull* g = Gs + r * HW + w * NU;
            #pragma unroll
            for (int k = 0; k < NU; k++) acc[k] = fma2(vv, g[k], acc[k]);
        }
        __syncthreads();
    }
    {
        ull* wout = (ull*)(Wm + lane * 96) + w * NU;
        #pragma unroll
        for (int k = 0; k < NU; k++) wout[k] = acc[k];
    }
    __syncthreads();

    // ---- Tapply: Wm2[i][grp10] = -(T^op * Wm)[i][grp8] ----
    {
        constexpr int NCG = WT / 8;
        for (int pos = tid; pos < 32 * NCG * 4; pos += 512) {
            int i = pos / (NCG * 4);
            int rem = pos - i * (NCG * 4);
            int cg = rem >> 2, k = rem & 3;
            int c = cg * 8 + 2 * k;
            ull a = 0ull;
            #pragma unroll
            for (int j = 0; j < 32; j++) {
                float tv = TRANS ? Tp[j * 33 + i] : Tp[i * 33 + j];
                a = fma2(pk2(-tv, -tv), *(const ull*)(Wm + j * 96 + c), a);
            }
            *(ull*)(Wm2 + i * W2STRIDE + cg * 10 + 2 * k) = a;
        }
    }
    __syncthreads();

    // ---- GEMM2: G += V * Wm2, 4 rows x 8 cols per thread ----
    {
        constexpr int NCG = WT / 8;
        const int npos = ((TN - o) >> 2) * NCG;
        for (int pos = tid; pos < npos; pos += 512) {
            int tg = pos / NCG, cg = pos - tg * NCG;
            int t0 = o + (tg << 2);
            float* gp = G + (size_t)t0 * FN + colbase + cg * 8;
            ull a[4][4];
            #pragma unroll
            for (int r = 0; r < 4; r++) {
                ulonglong2 q0 = ((const ulonglong2*)(gp + r * FN))[0];
                ulonglong2 q1 = ((const ulonglong2*)(gp + r * FN))[1];
                a[r][0] = q0.x; a[r][1] = q0.y; a[r][2] = q1.x; a[r][3] = q1.y;
            }
            const float* vr0 = Vp + (size_t)t0 * 33;         // immediate-offset rows
            const float* vr1 = vr0 + 33;
            const float* vr2 = vr1 + 33;
            const float* vr3 = vr2 + 33;
            const float* w2base = Wm2 + cg * 10;
            #pragma unroll 4
            for (int i = 0; i < 32; i++) {
                const ull* wp = (const ull*)(w2base + i * W2STRIDE);
                ull w0 = wp[0], w1 = wp[1], w2 = wp[2], w3 = wp[3];
                float v0 = vr0[i], v1 = vr1[i], v2 = vr2[i], v3 = vr3[i];
                ull vv0 = pk2(v0, v0), vv1 = pk2(v1, v1);
                ull vv2 = pk2(v2, v2), vv3 = pk2(v3, v3);
                a[0][0] = fma2(vv0, w0, a[0][0]); a[0][1] = fma2(vv0, w1, a[0][1]);
                a[0][2] = fma2(vv0, w2, a[0][2]); a[0][3] = fma2(vv0, w3, a[0][3]);
                a[1][0] = fma2(vv1, w0, a[1][0]); a[1][1] = fma2(vv1, w1, a[1][1]);
                a[1][2] = fma2(vv1, w2, a[1][2]); a[1][3] = fma2(vv1, w3, a[1][3]);
                a[2][0] = fma2(vv2, w0, a[2][0]); a[2][1] = fma2(vv2, w1, a[2][1]);
                a[2][2] = fma2(vv2, w2, a[2][2]); a[2][3] = fma2(vv2, w3, a[2][3]);
                a[3][0] = fma2(vv3, w0, a[3][0]); a[3][1] = fma2(vv3, w1, a[3][1]);
                a[3][2] = fma2(vv3, w2, a[3][2]); a[3][3] = fma2(vv3, w3, a[3][3]);
            }
            #pragma unroll
            for (int r = 0; r < 4; r++) {
                ulonglong2 q0, q1;
                q0.x = a[r][0]; q0.y = a[r][1]; q1.x = a[r][2]; q1.y = a[r][3];
                ((ulonglong2*)(gp + r * FN))[0] = q0;
                ((ulonglong2*)(gp + r * FN))[1] = q1;
            }
        }
    }
    __syncthreads();
}

__device__ void panel_factor(float* Vp, float* taus, float* sred, float* wred,
                             float* scal, int o, int tid)
{
    const int lane = tid & 31, w = tid >> 5;
    for (int i = 0; i < NB; i++) {
        const int prow = o + i;
        float val = 0.f;
        if (tid >= prow) val = VP(tid, i);
        if (tid == prow) scal[0] = val;
        float sq = (tid > prow) ? val * val : 0.f;
        sq = wsum(sq);
        if (lane == 0) sred[w] = sq;
        __syncthreads();
        if (tid == 0) {
            float s2 = 0.f;
            #pragma unroll
            for (int k = 0; k < 16; k++) s2 += sred[k];
            float alpha = scal[0], tau, sc;
            if (s2 == 0.f) { tau = 0.f; sc = 0.f; }
            else {
                float beta = -copysignf(sqrtf(alpha * alpha + s2), alpha);
                tau = (beta - alpha) / beta;
                sc = 1.f / (alpha - beta);
            }
            scal[1] = tau; scal[2] = sc; taus[o + i] = tau;
        }
        __syncthreads();
        const float tau = scal[1], sc = scal[2];
        if (tid > prow)       VP(tid, i) = val * sc;
        else if (tid == prow) VP(tid, i) = 1.f;
        __syncthreads();
        if (tau != 0.f && i < NB - 1) {
            const int c0 = w, c1 = w + 16;
            float p0 = 0.f, p1 = 0.f;
            for (int t = prow + lane; t < TN; t += 32) {
                float vi = VP(t, i);
                p0 += vi * VP(t, c0);
                p1 += vi * VP(t, c1);
            }
            p0 = wsum(p0); p1 = wsum(p1);
            if (lane == 0) { wred[c0] = p0; wred[c1] = p1; }
            __syncthreads();
            float tw = tau * wred[lane];
            if (lane > i) {
                for (int t = prow + w; t < TN; t += 16)
                    VP(t, lane) -= tw * VP(t, i);
            }
            __syncthreads();
        }
    }
}

__device__ void build_T(const float* Vp, float* B, float* Tp, const float* taus,
                        int o, int tid)
{
    const int lane = tid & 31, w = tid >> 5;
    for (int i = 1; i < NB; i++) {
        for (int j = w; j < i; j += 16) {
            float p = 0.f;
            for (int t = o + i + lane; t < TN; t += 32)
                p += VP(t, j) * VP(t, i);
            p = wsum(p);
            if (lane == 0) B[j * 32 + i] = p;
        }
    }
    __syncthreads();
    if (w == 0) {
        for (int i = 0; i < NB; i++) {
            float ti = taus[o + i];
            float a = 0.f;
            for (int k = 0; k < i; k++)
                a += Tp[lane * 33 + k] * B[k * 32 + i];
            float tv = (lane < i) ? -ti * a : (lane == i ? ti : 0.f);
            Tp[lane * 33 + i] = tv;
            __syncwarp();
        }
    }
    __syncthreads();
}

// orgqr panel formation: Q[:, o:o+32] = E_p - V * (T * L0^T)
__device__ void form_panel(float* G, const float* Vp, const float* Tp,
                           float* M, int o, int tid)
{
    const int lane = tid & 31, w = tid >> 5;
    for (int pos = tid; pos < 32 * 32; pos += 512) {
        int i = pos >> 5, c = pos & 31;
        float a = 0.f;
        #pragma unroll 8
        for (int j = 0; j < 32; j++)
            a += Tp[i * 33 + j] * VP(o + c, j);
        M[i * 32 + c] = a;
    }
    __syncthreads();
    for (int t = o + w; t < TN; t += 16) {
        float q = (t == o + lane) ? 1.f : 0.f;
        const float* vr = Vp + (size_t)t * 33;
        #pragma unroll 8
        for (int j = 0; j < 32; j++)
            q -= vr[j] * M[j * 32 + lane];
        G[(size_t)t * FN + o + lane] = q;
    }
    for (int idx = tid; idx < o * 32; idx += 512) {
        int t = idx >> 5, c = idx & 31;
        G[(size_t)t * FN + o + c] = 0.f;
    }
    __syncthreads();
}

// SMEM (floats): Vp 16896 | Ts 4224 | Wm 3072 | Wm2 3840 | taus 128 | sred 16 | wred 32 | scal 4
#define SM_FLOATS (16896 + 4224 + 3072 + 3840 + 128 + 16 + 32 + 4)
#define SM_BYTES  (SM_FLOATS * 4)

__global__ __launch_bounds__(512, 2) void qr_kernel(float* __restrict__ Aall)
{
    extern __shared__ float sm[];
    float* Vp   = sm;                 // 16896
    float* Ts   = Vp + 16896;         // 4224
    float* Wm   = Ts + 4224;          // 3072
    float* Wm2  = Wm + 3072;          // 3840 (also GEMM1 staging + build_T B)
    float* taus = Wm2 + 3840;         // 128
    float* sred = taus + 128;         // 16
    float* wred = sred + 16;          // 32
    float* scal = wred + 32;          // 4

    const int b = blockIdx.x;
    float* A = Aall + (size_t)b * TN * FN;
    const int tid = threadIdx.x;
    const int lane = tid & 31, w = tid >> 5;

    // ---------------- geqrf (blocked) ----------------
    for (int p = 0; p < 4; p++) {
        const int o = p * 32;
        for (int t = o + w; t < TN; t += 16)
            VP(t, lane) = A[(size_t)t * FN + o + lane];
        __syncthreads();
        panel_factor(Vp, taus, sred, wred, scal, o, tid);
        for (int pos = tid; pos < 32 * 32; pos += 512) {
            int i = pos >> 5, r = pos & 31;
            if (r < i) VP(o + r, i) = 0.f;
        }
        __syncthreads();
        float* Tp = Ts + p * 1056;
        build_T(Vp, Wm2, Tp, taus, o, tid);
        if (p == 0)      block_apply<96, true>(A, 0,  32,  Vp, Tp, Wm, Wm2, tid);
        else if (p == 1) block_apply<64, true>(A, 32, 64,  Vp, Tp, Wm, Wm2, tid);
        else if (p == 2) block_apply<32, true>(A, 64, 96,  Vp, Tp, Wm, Wm2, tid);
        if (p != 3) {   // panel 3 stays resident in SMEM for orgqr
            for (int t = o + w; t < TN; t += 16)
                A[(size_t)t * FN + o + lane] = VP(t, lane);
            __syncthreads();
        }
    }

    // ---------------- orgqr (blocked, backward) ----------------
    for (int p = 3; p >= 0; p--) {
        const int o = p * 32;
        if (p != 3) {
            for (int t = o + w; t < TN; t += 16)
                VP(t, lane) = A[(size_t)t * FN + o + lane];
            __syncthreads();
        }
        const float* Tp = Ts + p * 1056;
        if (p == 0)      block_apply<96, false>(A, 0,  32, Vp, Tp, Wm, Wm2, tid);
        else if (p == 1) block_apply<64, false>(A, 32, 64, Vp, Tp, Wm, Wm2, tid);
        else if (p == 2) block_apply<32, false>(A, 64, 96, Vp, Tp, Wm, Wm2, tid);
        form_panel(A, Vp, Tp, Wm, o, tid);
    }
}

// ============================================================
extern "C" void kernel_launch(void* const* d_in, const int* in_sizes, int n_in,
                              void* d_out, int out_size)
{
    const float* x    = (const float*)d_in[0];
    const float* W    = (const float*)d_in[1];
    const float* bias = (const float*)d_in[2];
    float* out = (float*)d_out;

    cudaFuncSetAttribute(qr_kernel, cudaFuncAttributeMaxDynamicSharedMemorySize, SM_BYTES);

    dim3 cgrid(TN / 64, BN);
    conv_kernel<<<cgrid, 256>>>(x, W, bias, out);
    qr_kernel<<<BN, 512, SM_BYTES>>>(out);
}

// round 7
// speedup vs baseline: 1.6912x; 1.0002x over previous
#include <cuda_runtime.h>

#define BN 256
#define TN 512
#define CN 128
#define FN 128
#define NB 32

typedef unsigned long long ull;

__device__ __forceinline__ ull pk2(float lo, float hi) {
    ull r; asm("mov.b64 %0, {%1, %2};" : "=l"(r) : "f"(lo), "f"(hi)); return r;
}
__device__ __forceinline__ void upk2(ull v, float& lo, float& hi) {
    asm("mov.b64 {%0, %1}, %2;" : "=f"(lo), "=f"(hi) : "l"(v));
}
__device__ __forceinline__ ull fma2(ull a, ull b, ull c) {
    ull d; asm("fma.rn.f32x2 %0, %1, %2, %3;" : "=l"(d) : "l"(a), "l"(b), "l"(c)); return d;
}
__device__ __forceinline__ float wsum(float v) {
    #pragma unroll
    for (int o = 16; o; o >>= 1) v += __shfl_xor_sync(0xffffffffu, v, o);
    return v;
}

// ============================================================
// Conv1D: y[b][t][f] = sum_{k,c} x[b][t+k-1][c] * W[k][c][f] + bias[f]
// ============================================================
__global__ __launch_bounds__(256) void conv_kernel(
    const float* __restrict__ x, const float* __restrict__ W,
    const float* __restrict__ bias, float* __restrict__ y)
{
    __shared__ float Xs[64][33];
    __shared__ float Ws[32][128];

    const int b = blockIdx.y, t0 = blockIdx.x * 64, tid = threadIdx.x;
    const int lane = tid & 31, warp = tid >> 5;
    const int cbase = lane * 4, rbase = warp * 8;

    ull acc2[8][2];
    #pragma unroll
    for (int i = 0; i < 8; i++) { acc2[i][0] = 0ull; acc2[i][1] = 0ull; }

    for (int k = 0; k < 3; k++) {
        for (int c0 = 0; c0 < CN; c0 += 32) {
            #pragma unroll
            for (int q = 0; q < 16; q++) {
                int e = tid + 256 * q, f = e & 127, cc = e >> 7;
                Ws[cc][f] = W[((size_t)(k * CN + c0 + cc)) * FN + f];
            }
            #pragma unroll
            for (int q = 0; q < 8; q++) {
                int e = tid + 256 * q, cc = e & 31, r = e >> 5;
                int t = t0 + r + k - 1;
                float v = 0.f;
                if (t >= 0 && t < TN) v = x[((size_t)b * TN + t) * CN + c0 + cc];
                Xs[r][cc] = v;
            }
            __syncthreads();
            #pragma unroll
            for (int cc = 0; cc < 32; cc++) {
                const ull* wp = (const ull*)&Ws[cc][cbase];
                ull w01 = wp[0], w23 = wp[1];
                #pragma unroll
                for (int i = 0; i < 8; i++) {
                    float xv = Xs[rbase + i][cc];
                    ull xx = pk2(xv, xv);
                    acc2[i][0] = fma2(xx, w01, acc2[i][0]);
                    acc2[i][1] = fma2(xx, w23, acc2[i][1]);
                }
            }
            __syncthreads();
        }
    }
    float b0 = bias[cbase], b1 = bias[cbase+1], b2 = bias[cbase+2], b3 = bias[cbase+3];
    #pragma unroll
    for (int i = 0; i < 8; i++) {
        int t = t0 + rbase + i;
        float4 o; float lo, hi;
        upk2(acc2[i][0], lo, hi); o.x = lo + b0; o.y = hi + b1;
        upk2(acc2[i][1], lo, hi); o.z = lo + b2; o.w = hi + b3;
        *(float4*)&y[((size_t)b * TN + t) * FN + cbase] = o;
    }
}

// ============================================================
// Blocked Householder QR (WY), one CTA per 512x128 matrix.
// Vp stride-33: conflict-free banks in BOTH row and column access,
// zero swizzle ALU (column index folds into LDS immediate offsets).
// ============================================================
#define VP(t,i)   Vp[(t) * 33 + (i)]
#define W2STRIDE  120   /* 32 rows x (12 groups x 10 floats) */

template<int WT, bool TRANS>
__device__ void block_apply(float* __restrict__ G, int o, int colbase,
                            const float* __restrict__ Vp, const float* __restrict__ Tp,
                            float* __restrict__ Wm, float* __restrict__ Wm2, int tid)
{
    const int lane = tid & 31, w = tid >> 5;
    constexpr int NU = WT / 32;      // ull per warp-row in GEMM1
    constexpr int HW = WT / 2;       // ull per staged row
    constexpr int TU = 32 * HW;      // ull per 32-row tile
    ull* Gs = (ull*)Wm2;             // staging buffer overlays Wm2

    // ---- GEMM1: Wm[i][c] = sum_t V[t][i]*G[t][colbase+c] (SMEM staged) ----
    ull acc[NU];
    #pragma unroll
    for (int k = 0; k < NU; k++) acc[k] = 0ull;
    const int ntiles = (TN - o) >> 5;
    for (int tile = 0; tile < ntiles; tile++) {
        const int t0 = o + (tile << 5);
        #pragma unroll
        for (int u = tid; u < TU; u += 512) {
            int r = u / HW, c = u - r * HW;
            Gs[u] = *(const ull*)(G + (size_t)(t0 + r) * FN + colbase + 2 * c);
        }
        __syncthreads();
        #pragma unroll
        for (int r = 0; r < 32; r++) {
            float v = VP(t0 + r, lane);
            ull vv = pk2(v, v);
            const ull* g = Gs + r * HW + w * NU;
            #pragma unroll
            for (int k = 0; k < NU; k++) acc[k] = fma2(vv, g[k], acc[k]);
        }
        __syncthreads();
    }
    {
        ull* wout = (ull*)(Wm + lane * 96) + w * NU;
        #pragma unroll
        for (int k = 0; k < NU; k++) wout[k] = acc[k];
    }
    __syncthreads();

    // ---- Tapply: Wm2[i][grp10] = -(T^op * Wm)[i][grp8] ----
    {
        constexpr int NCG = WT / 8;
        for (int pos = tid; pos < 32 * NCG * 4; pos += 512) {
            int i = pos / (NCG * 4);
            int rem = pos - i * (NCG * 4);
            int cg = rem >> 2, k = rem & 3;
            int c = cg * 8 + 2 * k;
            ull a = 0ull;
            #pragma unroll
            for (int j = 0; j < 32; j++) {
                float tv = TRANS ? Tp[j * 33 + i] : Tp[i * 33 + j];
                a = fma2(pk2(-tv, -tv), *(const ull*)(Wm + j * 96 + c), a);
            }
            *(ull*)(Wm2 + i * W2STRIDE + cg * 10 + 2 * k) = a;
        }
    }
    __syncthreads();

    // ---- GEMM2: G += V * Wm2, 4 rows x 8 cols per thread ----
    {
        constexpr int NCG = WT / 8;
        const int npos = ((TN - o) >> 2) * NCG;
        for (int pos = tid; pos < npos; pos += 512) {
            int tg = pos / NCG, cg = pos - tg * NCG;
            int t0 = o + (tg << 2);
            float* gp = G + (size_t)t0 * FN + colbase + cg * 8;
            ull a[4][4];
            #pragma unroll
            for (int r = 0; r < 4; r++) {
                ulonglong2 q0 = ((const ulonglong2*)(gp + r * FN))[0];
                ulonglong2 q1 = ((const ulonglong2*)(gp + r * FN))[1];
                a[r][0] = q0.x; a[r][1] = q0.y; a[r][2] = q1.x; a[r][3] = q1.y;
            }
            const float* vr0 = Vp + (size_t)t0 * 33;         // immediate-offset rows
            const float* vr1 = vr0 + 33;
            const float* vr2 = vr1 + 33;
            const float* vr3 = vr2 + 33;
            const float* w2base = Wm2 + cg * 10;
            #pragma unroll 4
            for (int i = 0; i < 32; i++) {
                const ull* wp = (const ull*)(w2base + i * W2STRIDE);
                ull w0 = wp[0], w1 = wp[1], w2 = wp[2], w3 = wp[3];
                float v0 = vr0[i], v1 = vr1[i], v2 = vr2[i], v3 = vr3[i];
                ull vv0 = pk2(v0, v0), vv1 = pk2(v1, v1);
                ull vv2 = pk2(v2, v2), vv3 = pk2(v3, v3);
                a[0][0] = fma2(vv0, w0, a[0][0]); a[0][1] = fma2(vv0, w1, a[0][1]);
                a[0][2] = fma2(vv0, w2, a[0][2]); a[0][3] = fma2(vv0, w3, a[0][3]);
                a[1][0] = fma2(vv1, w0, a[1][0]); a[1][1] = fma2(vv1, w1, a[1][1]);
                a[1][2] = fma2(vv1, w2, a[1][2]); a[1][3] = fma2(vv1, w3, a[1][3]);
                a[2][0] = fma2(vv2, w0, a[2][0]); a[2][1] = fma2(vv2, w1, a[2][1]);
                a[2][2] = fma2(vv2, w2, a[2][2]); a[2][3] = fma2(vv2, w3, a[2][3]);
                a[3][0] = fma2(vv3, w0, a[3][0]); a[3][1] = fma2(vv3, w1, a[3][1]);
                a[3][2] = fma2(vv3, w2, a[3][2]); a[3][3] = fma2(vv3, w3, a[3][3]);
            }
            #pragma unroll
            for (int r = 0; r < 4; r++) {
                ulonglong2 q0, q1;
                q0.x = a[r][0]; q0.y = a[r][1]; q1.x = a[r][2]; q1.y = a[r][3];
                ((ulonglong2*)(gp + r * FN))[0] = q0;
                ((ulonglong2*)(gp + r * FN))[1] = q1;
            }
        }
    }
    __syncthreads();
}

__device__ void panel_factor(float* Vp, float* taus, float* sred, float* wred,
                             float* scal, int o, int tid)
{
    const int lane = tid & 31, w = tid >> 5;
    for (int i = 0; i < NB; i++) {
        const int prow = o + i;
        float val = 0.f;
        if (tid >= prow) val = VP(tid, i);
        if (tid == prow) scal[0] = val;
        float sq = (tid > prow) ? val * val : 0.f;
        sq = wsum(sq);
        if (lane == 0) sred[w] = sq;
        __syncthreads();
        if (tid == 0) {
            float s2 = 0.f;
            #pragma unroll
            for (int k = 0; k < 16; k++) s2 += sred[k];
            float alpha = scal[0], tau, sc;
            if (s2 == 0.f) { tau = 0.f; sc = 0.f; }
            else {
                float beta = -copysignf(sqrtf(alpha * alpha + s2), alpha);
                tau = (beta - alpha) / beta;
                sc = 1.f / (alpha - beta);
            }
            scal[1] = tau; scal[2] = sc; taus[o + i] = tau;
        }
        __syncthreads();
        const float tau = scal[1], sc = scal[2];
        if (tid > prow)       VP(tid, i) = val * sc;
        else if (tid == prow) VP(tid, i) = 1.f;
        __syncthreads();
        if (tau != 0.f && i < NB - 1) {
            const int c0 = w, c1 = w + 16;
            float p0 = 0.f, p1 = 0.f;
            for (int t = prow + lane; t < TN; t += 32) {
                float vi = VP(t, i);
                p0 += vi * VP(t, c0);
                p1 += vi * VP(t, c1);
            }
            p0 = wsum(p0); p1 = wsum(p1);
            if (lane == 0) { wred[c0] = p0; wred[c1] = p1; }
            __syncthreads();
            float tw = tau * wred[lane];
            if (lane > i) {
                for (int t = prow + w; t < TN; t += 16)
                    VP(t, lane) -= tw * VP(t, i);
            }
            __syncthreads();
        }
    }
}

__device__ void build_T(const float* Vp, float* B, float* Tp, const float* taus,
                        int o, int tid)
{
    const int lane = tid & 31, w = tid >> 5;
    for (int i = 1; i < NB; i++) {
        for (int j = w; j < i; j += 16) {
            float p = 0.f;
            for (int t = o + i + lane; t < TN; t += 32)
                p += VP(t, j) * VP(t, i);
            p = wsum(p);
            if (lane == 0) B[j * 32 + i] = p;
        }
    }
    __syncthreads();
    if (w == 0) {
        for (int i = 0; i < NB; i++) {
            float ti = taus[o + i];
            float a = 0.f;
            for (int k = 0; k < i; k++)
                a += Tp[lane * 33 + k] * B[k * 32 + i];
            float tv = (lane < i) ? -ti * a : (lane == i ? ti : 0.f);
            Tp[lane * 33 + i] = tv;
            __syncwarp();
        }
    }
    __syncthreads();
}

// orgqr panel formation: Q[:, o:o+32] = E_p - V * (T * L0^T)
__device__ void form_panel(float* G, const float* Vp, const float* Tp,
                           float* M, int o, int tid)
{
    const int lane = tid & 31, w = tid >> 5;
    for (int pos = tid; pos < 32 * 32; pos += 512) {
        int i = pos >> 5, c = pos & 31;
        float a = 0.f;
        #pragma unroll 8
        for (int j = 0; j < 32; j++)
            a += Tp[i * 33 + j] * VP(o + c, j);
        M[i * 32 + c] = a;
    }
    __syncthreads();
    for (int t = o + w; t < TN; t += 16) {
        float q = (t == o + lane) ? 1.f : 0.f;
        const float* vr = Vp + (size_t)t * 33;
        #pragma unroll 8
        for (int j = 0; j < 32; j++)
            q -= vr[j] * M[j * 32 + lane];
        G[(size_t)t * FN + o + lane] = q;
    }
    for (int idx = tid; idx < o * 32; idx += 512) {
        int t = idx >> 5, c = idx & 31;
        G[(size_t)t * FN + o + c] = 0.f;
    }
    __syncthreads();
}

// SMEM (floats): Vp 16896 | Ts 4224 | Wm 3072 | Wm2 3840 | taus 128 | sred 16 | wred 32 | scal 4
#define SM_FLOATS (16896 + 4224 + 3072 + 3840 + 128 + 16 + 32 + 4)
#define SM_BYTES  (SM_FLOATS * 4)

__global__ __launch_bounds__(512, 2) void qr_kernel(float* __restrict__ Aall)
{
    extern __shared__ float sm[];
    float* Vp   = sm;                 // 16896
    float* Ts   = Vp + 16896;         // 4224
    float* Wm   = Ts + 4224;          // 3072
    float* Wm2  = Wm + 3072;          // 3840 (also GEMM1 staging + build_T B)
    float* taus = Wm2 + 3840;         // 128
    float* sred = taus + 128;         // 16
    float* wred = sred + 16;          // 32
    float* scal = wred + 32;          // 4

    const int b = blockIdx.x;
    float* A = Aall + (size_t)b * TN * FN;
    const int tid = threadIdx.x;
    const int lane = tid & 31, w = tid >> 5;

    // ---------------- geqrf (blocked) ----------------
    for (int p = 0; p < 4; p++) {
        const int o = p * 32;
        for (int t = o + w; t < TN; t += 16)
            VP(t, lane) = A[(size_t)t * FN + o + lane];
        __syncthreads();
        panel_factor(Vp, taus, sred, wred, scal, o, tid);
        for (int pos = tid; pos < 32 * 32; pos += 512) {
            int i = pos >> 5, r = pos & 31;
            if (r < i) VP(o + r, i) = 0.f;
        }
        __syncthreads();
        float* Tp = Ts + p * 1056;
        build_T(Vp, Wm2, Tp, taus, o, tid);
        if (p == 0)      block_apply<96, true>(A, 0,  32,  Vp, Tp, Wm, Wm2, tid);
        else if (p == 1) block_apply<64, true>(A, 32, 64,  Vp, Tp, Wm, Wm2, tid);
        else if (p == 2) block_apply<32, true>(A, 64, 96,  Vp, Tp, Wm, Wm2, tid);
        if (p != 3) {   // panel 3 stays resident in SMEM for orgqr
            for (int t = o + w; t < TN; t += 16)
                A[(size_t)t * FN + o + lane] = VP(t, lane);
            __syncthreads();
        }
    }

    // ---------------- orgqr (blocked, backward) ----------------
    for (int p = 3; p >= 0; p--) {
        const int o = p * 32;
        if (p != 3) {
            for (int t = o + w; t < TN; t += 16)
                VP(t, lane) = A[(size_t)t * FN + o + lane];
            __syncthreads();
        }
        const float* Tp = Ts + p * 1056;
        if (p == 0)      block_apply<96, false>(A, 0,  32, Vp, Tp, Wm, Wm2, tid);
        else if (p == 1) block_apply<64, false>(A, 32, 64, Vp, Tp, Wm, Wm2, tid);
        else if (p == 2) block_apply<32, false>(A, 64, 96, Vp, Tp, Wm, Wm2, tid);
        form_panel(A, Vp, Tp, Wm, o, tid);
    }
}

// ============================================================
extern "C" void kernel_launch(void* const* d_in, const int* in_sizes, int n_in,
                              void* d_out, int out_size)
{
    const float* x    = (const float*)d_in[0];
    const float* W    = (const float*)d_in[1];
    const float* bias = (const float*)d_in[2];
    float* out = (float*)d_out;

    cudaFuncSetAttribute(qr_kernel, cudaFuncAttributeMaxDynamicSharedMemorySize, SM_BYTES);

    dim3 cgrid(TN / 64, BN);
    conv_kernel<<<cgrid, 256>>>(x, W, bias, out);
    qr_kernel<<<BN, 512, SM_BYTES>>>(out);
}